// round 16
// baseline (speedup 1.0000x reference)
#include <cuda_runtime.h>
#include <cuda_fp16.h>
#include <math.h>
#include <stdint.h>

// Problem constants
#define Bsz 2
#define Sq  2048
#define Dm  512
#define Vv  32000
#define Ll  3
#define ROWS (Bsz*Sq)      // 4096
#define BD   (ROWS*Dm)     // 2097152
#define SSZ  (Bsz*Sq*Sq)   // 8388608
#define INV_SCALE 0.125f

// ---------------- fp32 scratch ----------------
__device__ float g_x[BD];
__device__ float g_out[BD];
__device__ float g_h[BD];
__device__ float g_h2[BD];
__device__ float g_t[BD];
__device__ float g_a[BD];
__device__ float g_rowsum[ROWS];    // vocab softmax sums
__device__ float g_rs2[ROWS];       // attention softmax sums

// ---------------- fp16 scratch ----------------
__device__ __half sx[BD];          // encoder state
__device__ __half so[BD];          // decoder state
__device__ __half sh[BD];          // attn-out
__device__ __half sh2[BD];         // attn2-out
__device__ __half sqkv[3*BD];      // Q | K | (V slot)
__device__ __half sp[SSZ];         // unnormalized exp-probs
__device__ __half svt[BD];         // V^T  [b][Dm][Sq]
__device__ __half sw[(long)Vv*Dm]; // packed weights^T

// ================= helpers =================
__device__ __forceinline__ uint32_t smem_u32(const void* p) {
    uint32_t a;
    asm("{ .reg .u64 t; cvta.to.shared.u64 t, %1; cvt.u32.u64 %0, t; }" : "=r"(a) : "l"(p));
    return a;
}
#define CP_ASYNC(dst, src) asm volatile("cp.async.cg.shared.global [%0], [%1], 16;" :: "r"(dst), "l"(src) : "memory")
#define CP_COMMIT()        asm volatile("cp.async.commit_group;" ::: "memory")
#define CP_WAIT(n)         asm volatile("cp.async.wait_group %0;" :: "n"(n) : "memory")

__device__ __forceinline__ void ldmx4(uint32_t& r0, uint32_t& r1, uint32_t& r2, uint32_t& r3, uint32_t a) {
    asm volatile("ldmatrix.sync.aligned.m8n8.x4.shared.b16 {%0,%1,%2,%3}, [%4];"
                 : "=r"(r0), "=r"(r1), "=r"(r2), "=r"(r3) : "r"(a));
}
__device__ __forceinline__ void mma_f16(float* d, const uint32_t* a, const uint32_t* b) {
    asm volatile(
        "mma.sync.aligned.m16n8k16.row.col.f32.f16.f16.f32 "
        "{%0,%1,%2,%3}, {%4,%5,%6,%7}, {%8,%9}, {%0,%1,%2,%3};"
        : "+f"(d[0]), "+f"(d[1]), "+f"(d[2]), "+f"(d[3])
        : "r"(a[0]), "r"(a[1]), "r"(a[2]), "r"(a[3]), "r"(b[0]), "r"(b[1]));
}
// SW128 swizzle for an R-row x 64-half (128B/row) tile. c = 16B chunk 0..7.
__device__ __forceinline__ uint32_t swz(int r, int c) {
    return (uint32_t)(r * 128 + ((c ^ (r & 7)) * 16));
}

// ================= GEMM: C = alpha * A @ B^T (+bias), fp16 x fp16 ===========
// A: [M,K] fp16; B: [N,K] fp16; fp32 accum.
// BM=128, BN=256, BK=64, 256 threads (8 warps: 2 M x 4 N, warp tile 64x64),
// 3-stage cp.async smem pipeline + double-buffered register fragments, 144KB smem.
// OUTM: 0 = fp32, 1 = fp16,
//       2 = exp() fp32 + atomic row sums (vocab softmax),
//       3 = exp() fp16 + atomic row sums (attention softmax; rowsum idx bz*M+row).
// Fused-output: global col cg -> out + (cg/outDiv)*bufStride + row*outDiv + cg%outDiv.
// TRANSV: column-buffer == vbuf written transposed into Cvt (V^T).
#define TILEA 16384
#define TILEB2 32768
#define STAGEB (TILEA + TILEB2)
#define GEMM_SMEM (3*STAGEB)

template<int OUTM, bool HAS_BIAS, bool TRANSV>
__global__ void __launch_bounds__(256) gemm1(
    const __half* __restrict__ A, const __half* __restrict__ B,
    const float* __restrict__ bias,
    float* __restrict__ C, __half* __restrict__ Ch, __half* __restrict__ Cvt,
    float* __restrict__ rowsum,
    int M, int N, int K, float alpha, long sA, long sB, long sC,
    int outDiv, long bufStride, int vbuf)
{
    extern __shared__ char smem[];
    const uint32_t sb = smem_u32(smem);
    const int tid = threadIdx.x, lane = tid & 31, wid = tid >> 5;
    const int wm = wid >> 2, wn = wid & 3;          // 2 M-warps x 4 N-warps
    const int bz = blockIdx.z;
    A += (long)bz * sA;
    B += (long)bz * sB;

    const long rA0 = (long)blockIdx.y * 128;
    const long rB0 = (long)blockIdx.x * 256;

    // loader: A = 1024 chunks (4/thread), B = 2048 chunks (8/thread)
    uint32_t soffA[4], soffB[8];
    long goffA[4], goffB[8];
    #pragma unroll
    for (int i = 0; i < 4; i++) {
        const int q = tid + i * 256;
        soffA[i] = swz(q >> 3, q & 7);
        goffA[i] = (long)(q >> 3) * K + (q & 7) * 8;
    }
    #pragma unroll
    for (int i = 0; i < 8; i++) {
        const int q = tid + i * 256;
        soffB[i] = swz(q >> 3, q & 7);
        goffB[i] = (long)(q >> 3) * K + (q & 7) * 8;
    }
    const __half* gA = A + rA0 * K;
    const __half* gB = B + rB0 * K;

    float acc[4][8][4];
    #pragma unroll
    for (int i = 0; i < 4; i++)
        #pragma unroll
        for (int j = 0; j < 8; j++)
            #pragma unroll
            for (int q = 0; q < 4; q++) acc[i][j][q] = 0.f;

    const int nk = K >> 6;

    auto load_tile = [&](int st, int k0) {
        const uint32_t s = sb + st * STAGEB;
        #pragma unroll
        for (int i = 0; i < 4; i++)
            CP_ASYNC(s + soffA[i], gA + goffA[i] + k0);
        #pragma unroll
        for (int i = 0; i < 8; i++)
            CP_ASYNC(s + TILEA + soffB[i], gB + goffB[i] + k0);
    };

    load_tile(0, 0);  CP_COMMIT();
    load_tile(1, 64); CP_COMMIT();

    const int arow = wm * 64 + (lane & 15);
    const int brow = wn * 64 + ((lane >> 4) << 3) + (lane & 7);
    const int asel = (lane >> 4);
    const int bsel = ((lane >> 3) & 1);

    int st = 0;
    for (int kt = 0; kt < nk; kt++) {
        if (kt + 1 < nk) { CP_WAIT(1); } else { CP_WAIT(0); }
        __syncthreads();
        if (kt + 2 < nk) {
            int st2 = st + 2; if (st2 >= 3) st2 -= 3;
            load_tile(st2, (kt + 2) << 6);
            CP_COMMIT();
        }

        const uint32_t s0  = sb + st * STAGEB;
        const uint32_t sA0 = s0, sB0 = s0 + TILEA;

        uint32_t ah[2][4][4];
        uint32_t bh[2][8][2];

        auto ldfr = [&](int ks, int pb) {
            const int achk = ks * 2 + asel;
            const int bchk = ks * 2 + bsel;
            #pragma unroll
            for (int mi = 0; mi < 4; mi++) {
                const uint32_t off = swz(arow + mi * 16, achk);
                ldmx4(ah[pb][mi][0], ah[pb][mi][1], ah[pb][mi][2], ah[pb][mi][3], sA0 + off);
            }
            #pragma unroll
            for (int nj = 0; nj < 4; nj++) {
                const uint32_t off = swz(brow + nj * 16, bchk);
                uint32_t t0, t1, t2, t3;
                ldmx4(t0, t1, t2, t3, sB0 + off);
                bh[pb][2*nj][0] = t0; bh[pb][2*nj][1] = t1;
                bh[pb][2*nj+1][0] = t2; bh[pb][2*nj+1][1] = t3;
            }
        };

        ldfr(0, 0);
        #pragma unroll
        for (int ks = 0; ks < 4; ks++) {
            const int cur = ks & 1;
            if (ks < 3) ldfr(ks + 1, cur ^ 1);
            #pragma unroll
            for (int mi = 0; mi < 4; mi++)
                #pragma unroll
                for (int ni = 0; ni < 8; ni++)
                    mma_f16(acc[mi][ni], ah[cur][mi], bh[cur][ni]);
        }
        st++; if (st >= 3) st = 0;
    }

    // epilogue
    const int ctile = blockIdx.x * 256;
    const int buf   = (ctile + wn * 64) / outDiv;
    const int cb    = ((ctile + wn * 64) % outDiv) + (lane & 3) * 2;
    const long rbase = rA0 + wm * 64 + (lane >> 2);
    const long base  = (long)bz * sC + (long)buf * bufStride;

    if (TRANSV && buf == vbuf) {
        #pragma unroll
        for (int mi = 0; mi < 4; mi++) {
            const long rt0 = rbase + mi * 16;
            const long rt1 = rt0 + 8;
            const long b0 = (rt0 >> 11) * ((long)Dm * Sq), p0 = rt0 & 2047;
            const long b1 = (rt1 >> 11) * ((long)Dm * Sq), p1 = rt1 & 2047;
            #pragma unroll
            for (int ni = 0; ni < 8; ni++) {
                const int cc = cb + ni * 8;
                Cvt[b0 + (long)cc * Sq + p0]       = __float2half(acc[mi][ni][0]);
                Cvt[b0 + (long)(cc + 1) * Sq + p0] = __float2half(acc[mi][ni][1]);
                Cvt[b1 + (long)cc * Sq + p1]       = __float2half(acc[mi][ni][2]);
                Cvt[b1 + (long)(cc + 1) * Sq + p1] = __float2half(acc[mi][ni][3]);
            }
        }
        return;
    }

    #pragma unroll
    for (int mi = 0; mi < 4; mi++) {
        float rs0 = 0.f, rs1 = 0.f;
        #pragma unroll
        for (int ni = 0; ni < 8; ni++) {
            const int cc = cb + ni * 8;
            float v00 = alpha * acc[mi][ni][0], v01 = alpha * acc[mi][ni][1];
            float v10 = alpha * acc[mi][ni][2], v11 = alpha * acc[mi][ni][3];
            if (HAS_BIAS) {
                v00 += bias[cc]; v01 += bias[cc + 1];
                v10 += bias[cc]; v11 += bias[cc + 1];
            }
            const long r0 = base + (rbase + mi * 16) * outDiv + cc;
            const long r1 = r0 + 8 * outDiv;
            if (OUTM == 0) {
                *(float2*)(C + r0) = {v00, v01};
                *(float2*)(C + r1) = {v10, v11};
            } else if (OUTM == 1) {
                *(__half2*)(Ch + r0) = __halves2half2(__float2half(v00), __float2half(v01));
                *(__half2*)(Ch + r1) = __halves2half2(__float2half(v10), __float2half(v11));
            } else {
                float e00 = __expf(v00), e01 = __expf(v01);
                float e10 = __expf(v10), e11 = __expf(v11);
                if (OUTM == 2) {
                    *(float2*)(C + r0) = {e00, e01};
                    *(float2*)(C + r1) = {e10, e11};
                } else {
                    *(__half2*)(Ch + r0) = __halves2half2(__float2half(e00), __float2half(e01));
                    *(__half2*)(Ch + r1) = __halves2half2(__float2half(e10), __float2half(e11));
                }
                rs0 += e00 + e01;
                rs1 += e10 + e11;
            }
        }
        if (OUTM == 2 || OUTM == 3) {
            #pragma unroll
            for (int o = 1; o < 4; o <<= 1) {
                rs0 += __shfl_xor_sync(0xffffffffu, rs0, o);
                rs1 += __shfl_xor_sync(0xffffffffu, rs1, o);
            }
            if ((lane & 3) == 0) {
                const long rr = (long)bz * M + rbase + mi * 16;
                atomicAdd(&rowsum[rr], rs0);
                atomicAdd(&rowsum[rr + 8], rs1);
            }
        }
    }
}

// normalize: probs = exp_vals * (1/rowsum[row])
__global__ void norml_kernel(float* __restrict__ data, const float* __restrict__ rowsum)
{
    long i = ((long)blockIdx.x * blockDim.x + threadIdx.x) * 4;
    const float inv = 1.f / rowsum[i / Vv];
    float4 v = *(float4*)(data + i);
    v.x *= inv; v.y *= inv; v.z *= inv; v.w *= inv;
    *(float4*)(data + i) = v;
}

// ================= conversion kernels =================
__global__ void convh(const float* __restrict__ in, __half* __restrict__ o, long n)
{
    long i = ((long)blockIdx.x * blockDim.x + threadIdx.x) * 4;
    if (i >= n) return;
    float4 v = *(const float4*)(in + i);
    __half2 a = __halves2half2(__float2half(v.x), __float2half(v.y));
    __half2 b = __halves2half2(__float2half(v.z), __float2half(v.w));
    *(uint2*)(o + i) = make_uint2(*(uint32_t*)&a, *(uint32_t*)&b);
}

// transpose + convert: fp32 [R,C] -> fp16 [C,R]
__global__ void __launch_bounds__(256) tconvh(
    const float* __restrict__ in, __half* __restrict__ o, int R, int C)
{
    __shared__ float t[32][33];
    const int c0 = blockIdx.x * 32, r0 = blockIdx.y * 32;
    const int tx = threadIdx.x, ty = threadIdx.y;
    #pragma unroll
    for (int j = 0; j < 32; j += 8)
        t[ty + j][tx] = in[(long)(r0 + ty + j) * C + c0 + tx];
    __syncthreads();
    #pragma unroll
    for (int j = 0; j < 32; j += 8) {
        long ofs = (long)(c0 + ty + j) * R + r0 + tx;
        o[ofs] = __float2half(t[tx][ty + j]);
    }
}

// batched transpose+convert of up to 3 square DxD weights
__global__ void __launch_bounds__(256) tconvh3(
    const float* __restrict__ w0, const float* __restrict__ w1, const float* __restrict__ w2,
    __half* __restrict__ o)
{
    __shared__ float t[32][33];
    const int z = blockIdx.z;
    const float* in = (z == 0) ? w0 : (z == 1) ? w1 : w2;
    __half* dst = o + (long)z * Dm * Dm;
    const int c0 = blockIdx.x * 32, r0 = blockIdx.y * 32;
    const int tx = threadIdx.x, ty = threadIdx.y;
    #pragma unroll
    for (int j = 0; j < 32; j += 8)
        t[ty + j][tx] = in[(long)(r0 + ty + j) * Dm + c0 + tx];
    __syncthreads();
    #pragma unroll
    for (int j = 0; j < 32; j += 8) {
        long ofs = (long)(c0 + ty + j) * Dm + r0 + tx;
        dst[ofs] = __float2half(t[tx][ty + j]);
    }
}

// ====== fused (rowscale?)+(silu?)+residual+LayerNorm, fp32 out + fp16 out ======
template<bool SILU, bool AFFINE, bool RS>
__global__ void __launch_bounds__(128) addln_kernel(
    const float* __restrict__ a, const float* __restrict__ res,
    const float* __restrict__ g, const float* __restrict__ bta,
    const float* __restrict__ rowsum,
    float* __restrict__ out, __half* __restrict__ oh)
{
    const int row = blockIdx.x;
    const int tid = threadIdx.x;
    float4 av = ((const float4*)(a   + (size_t)row * Dm))[tid];
    float4 rv = ((const float4*)(res + (size_t)row * Dm))[tid];
    float v[4] = {av.x, av.y, av.z, av.w};
    float r[4] = {rv.x, rv.y, rv.z, rv.w};
    const float rsc = RS ? (1.f / rowsum[row]) : 1.f;

    float s = 0.f, s2 = 0.f;
    #pragma unroll
    for (int i = 0; i < 4; i++) {
        float t = RS ? (v[i] * rsc) : v[i];
        t = SILU ? (t / (1.f + __expf(-t))) : t;
        t += r[i];
        v[i] = t;
        s += t; s2 += t * t;
    }
    __shared__ float ss[4], ss2[4];
    #pragma unroll
    for (int o = 16; o; o >>= 1) {
        s  += __shfl_xor_sync(0xffffffffu, s,  o);
        s2 += __shfl_xor_sync(0xffffffffu, s2, o);
    }
    const int w = tid >> 5, lane = tid & 31;
    if (lane == 0) { ss[w] = s; ss2[w] = s2; }
    __syncthreads();
    s  = ss[0]  + ss[1]  + ss[2]  + ss[3];
    s2 = ss2[0] + ss2[1] + ss2[2] + ss2[3];

    const float mean = s * (1.f / Dm);
    const float var  = s2 * (1.f / Dm) - mean * mean;
    const float inv  = rsqrtf(var + 1e-5f);

    float ov[4];
    #pragma unroll
    for (int i = 0; i < 4; i++) {
        float yv = (v[i] - mean) * inv;
        if (AFFINE) {
            const int c = tid * 4 + i;
            yv = yv * g[c] + bta[c];
        }
        ov[i] = yv;
    }
    float4 o4 = {ov[0], ov[1], ov[2], ov[3]};
    ((float4*)(out + (size_t)row * Dm))[tid] = o4;
    __half2 h0 = __halves2half2(__float2half(ov[0]), __float2half(ov[1]));
    __half2 h1 = __halves2half2(__float2half(ov[2]), __float2half(ov[3]));
    ((uint2*)(oh + (size_t)row * Dm))[tid] = make_uint2(*(uint32_t*)&h0, *(uint32_t*)&h1);
}

// ================= host-side orchestration =================
struct Ptrs {
    float *gx, *gout, *gh, *gh2, *gt, *ga, *grs, *grs2;
    __half *x1, *o1, *h1, *h21, *q1, *k1, *p1, *vt1, *w1;
};

static void G(const __half* A, const __half* B,
              const float* bias, float* C, __half* Ch, int outm,
              int M, int N, int K, float alpha, int batch,
              long sA, long sB, long sC,
              int outDiv = 0, long bufStride = 0, float* rowsum = nullptr)
{
    if (outDiv == 0) outDiv = N;
    dim3 grid(N / 256, M / 128, batch), block(256);
    if (outm == 3)      gemm1<3, false, false><<<grid, block, GEMM_SMEM>>>(A, B, bias, C, Ch, nullptr, rowsum, M, N, K, alpha, sA, sB, sC, outDiv, bufStride, -1);
    else if (outm == 2) gemm1<2, false, false><<<grid, block, GEMM_SMEM>>>(A, B, bias, C, Ch, nullptr, rowsum, M, N, K, alpha, sA, sB, sC, outDiv, bufStride, -1);
    else if (outm == 1) gemm1<1, false, false><<<grid, block, GEMM_SMEM>>>(A, B, bias, C, Ch, nullptr, nullptr, M, N, K, alpha, sA, sB, sC, outDiv, bufStride, -1);
    else if (bias)      gemm1<0, true , false><<<grid, block, GEMM_SMEM>>>(A, B, bias, C, Ch, nullptr, nullptr, M, N, K, alpha, sA, sB, sC, outDiv, bufStride, -1);
    else                gemm1<0, false, false><<<grid, block, GEMM_SMEM>>>(A, B, bias, C, Ch, nullptr, nullptr, M, N, K, alpha, sA, sB, sC, outDiv, bufStride, -1);
}

static void Gp(const __half* A, const __half* B, __half* Ch, __half* Cvt, int vbuf,
               int M, int N, int K)
{
    dim3 grid(N / 256, M / 128, 1), block(256);
    gemm1<1, false, true><<<grid, block, GEMM_SMEM>>>(A, B, nullptr, nullptr, Ch, Cvt, nullptr,
                                                      M, N, K, 1.f, 0, 0, 0, Dm, (long)BD, vbuf);
}

static void tconv(const float* in, __half* o, int R, int C) {
    dim3 grid(C / 32, R / 32), block(32, 8);
    tconvh<<<grid, block>>>(in, o, R, C);
}
static void tconvN(const float* w0, const float* w1, const float* w2, __half* o, int nz) {
    dim3 grid(Dm / 32, Dm / 32, nz), block(32, 8);
    tconvh3<<<grid, block>>>(w0, w1, w2, o);
}

static void run_attn(const Ptrs& P,
                     const __half* q_in, const __half* c_in,
                     const float* wq, const float* wk, const float* wv,
                     const float* resid, float* outp, __half* out_h)
{
    if (q_in == c_in) {
        tconvN(wq, wk, wv, P.w1, 3);
        Gp(q_in, P.w1, P.q1, P.vt1, 2, ROWS, 3 * Dm, Dm);
    } else {
        tconv(wq, P.w1, Dm, Dm);
        G(q_in, P.w1, nullptr, nullptr, P.q1, 1, ROWS, Dm, Dm, 1.f, 1, 0, 0, 0);
        tconvN(wk, wv, nullptr, P.w1, 2);
        Gp(c_in, P.w1, P.k1, P.vt1, 1, ROWS, 2 * Dm, Dm);
    }

    // scores GEMM writes exp(score) fp16 + row sums (no separate softmax)
    cudaMemsetAsync(P.grs2, 0, ROWS * sizeof(float));
    G(P.q1, P.k1, nullptr, nullptr, P.p1, 3, Sq, Sq, Dm, INV_SCALE, Bsz,
      (long)Sq * Dm, (long)Sq * Dm, (long)Sq * Sq, 0, 0, P.grs2);
    // attn[b] = Pexp[b] @ V[b]  (unnormalized)
    G(P.p1, P.vt1, nullptr, P.ga, nullptr, 0, Sq, Dm, Sq, 1.f, Bsz,
      (long)Sq * Sq, (long)Sq * Dm, (long)Sq * Dm);
    // normalize by rowsum inside addln
    addln_kernel<false, false, true><<<ROWS, 128>>>(P.ga, resid, nullptr, nullptr, P.grs2, outp, out_h);
}

extern "C" void kernel_launch(void* const* d_in, const int* in_sizes, int n_in,
                              void* d_out, int out_size)
{
    const float* x       = (const float*)d_in[0];
    const float* y       = (const float*)d_in[1];
    const float* enc_wq  = (const float*)d_in[2];
    const float* enc_wk  = (const float*)d_in[3];
    const float* enc_wv  = (const float*)d_in[4];
    const float* enc_fw  = (const float*)d_in[5];
    const float* enc_fb  = (const float*)d_in[6];
    const float* enc_g   = (const float*)d_in[7];
    const float* enc_b   = (const float*)d_in[8];
    const float* dec_swq = (const float*)d_in[9];
    const float* dec_swk = (const float*)d_in[10];
    const float* dec_swv = (const float*)d_in[11];
    const float* dec_cwq = (const float*)d_in[12];
    const float* dec_cwk = (const float*)d_in[13];
    const float* dec_cwv = (const float*)d_in[14];
    const float* dec_fw  = (const float*)d_in[15];
    const float* dec_fb  = (const float*)d_in[16];
    const float* dec_g   = (const float*)d_in[17];
    const float* dec_b   = (const float*)d_in[18];
    const float* fc_w    = (const float*)d_in[19];

    cudaFuncSetAttribute(gemm1<0, false, false>, cudaFuncAttributeMaxDynamicSharedMemorySize, GEMM_SMEM);
    cudaFuncSetAttribute(gemm1<0, true , false>, cudaFuncAttributeMaxDynamicSharedMemorySize, GEMM_SMEM);
    cudaFuncSetAttribute(gemm1<1, false, false>, cudaFuncAttributeMaxDynamicSharedMemorySize, GEMM_SMEM);
    cudaFuncSetAttribute(gemm1<2, false, false>, cudaFuncAttributeMaxDynamicSharedMemorySize, GEMM_SMEM);
    cudaFuncSetAttribute(gemm1<3, false, false>, cudaFuncAttributeMaxDynamicSharedMemorySize, GEMM_SMEM);
    cudaFuncSetAttribute(gemm1<1, false, true >, cudaFuncAttributeMaxDynamicSharedMemorySize, GEMM_SMEM);

    Ptrs P;
    cudaGetSymbolAddress((void**)&P.gx,   g_x);
    cudaGetSymbolAddress((void**)&P.gout, g_out);
    cudaGetSymbolAddress((void**)&P.gh,   g_h);
    cudaGetSymbolAddress((void**)&P.gh2,  g_h2);
    cudaGetSymbolAddress((void**)&P.gt,   g_t);
    cudaGetSymbolAddress((void**)&P.ga,   g_a);
    cudaGetSymbolAddress((void**)&P.grs,  g_rowsum);
    cudaGetSymbolAddress((void**)&P.grs2, g_rs2);
    cudaGetSymbolAddress((void**)&P.x1,  sx);
    cudaGetSymbolAddress((void**)&P.o1,  so);
    cudaGetSymbolAddress((void**)&P.h1,  sh);
    cudaGetSymbolAddress((void**)&P.h21, sh2);
    cudaGetSymbolAddress((void**)&P.q1,  sqkv);
    P.k1 = P.q1 + BD;
    cudaGetSymbolAddress((void**)&P.p1,  sp);
    cudaGetSymbolAddress((void**)&P.vt1, svt);
    cudaGetSymbolAddress((void**)&P.w1,  sw);

    cudaMemcpyAsync(P.gx,   x, (size_t)BD * sizeof(float), cudaMemcpyDeviceToDevice);
    cudaMemcpyAsync(P.gout, y, (size_t)BD * sizeof(float), cudaMemcpyDeviceToDevice);
    cudaMemsetAsync(P.grs, 0, ROWS * sizeof(float));
    convh<<<(BD / 4 + 255) / 256, 256>>>(x, P.x1, BD);
    convh<<<(BD / 4 + 255) / 256, 256>>>(y, P.o1, BD);

    const long DD = (long)Dm * Dm;

    // -------- encoder stacks --------
    for (int i = 0; i < Ll; i++) {
        run_attn(P, P.x1, P.x1,
                 enc_wq + i * DD, enc_wk + i * DD, enc_wv + i * DD,
                 P.gx, P.gh, P.h1);
        tconv(enc_fw + i * DD, P.w1, Dm, Dm);
        G(P.h1, P.w1, enc_fb + i * Dm, P.gt, nullptr, 0, ROWS, Dm, Dm, 1.f, 1, 0, 0, 0);
        addln_kernel<true, true, false><<<ROWS, 128>>>(P.gt, P.gh, enc_g + i * Dm, enc_b + i * Dm, nullptr, P.gx, P.x1);
    }

    // -------- decoder stacks --------
    for (int i = 0; i < Ll; i++) {
        run_attn(P, P.x1, P.x1,
                 dec_swq + i * DD, dec_swk + i * DD, dec_swv + i * DD,
                 P.gx, P.gh, P.h1);
        run_attn(P, P.h1, P.o1,
                 dec_cwq + i * DD, dec_cwk + i * DD, dec_cwv + i * DD,
                 P.gh, P.gh2, P.h21);
        tconv(dec_fw + i * DD, P.w1, Dm, Dm);
        G(P.h21, P.w1, dec_fb + i * Dm, P.gt, nullptr, 0, ROWS, Dm, Dm, 1.f, 1, 0, 0, 0);
        addln_kernel<true, true, false><<<ROWS, 128>>>(P.gt, P.gh2, dec_g + i * Dm, dec_b + i * Dm, nullptr, P.gout, P.o1);
    }

    // -------- vocab head: GEMM writes exp(logits) + row sums, then normalize --------
    tconv(fc_w, P.w1, Dm, Vv);
    float* probs = (float*)d_out;
    G(P.o1, P.w1, nullptr, probs, nullptr, 2, ROWS, Vv, Dm, 1.f, 1, 0, 0, 0, 0, 0, P.grs);
    norml_kernel<<<(int)(((long)ROWS * Vv / 4) / 256), 256>>>(probs, P.grs);
}

// round 17
// speedup vs baseline: 1.3057x; 1.3057x over previous
#include <cuda_runtime.h>
#include <cuda_fp16.h>
#include <math.h>
#include <stdint.h>

// Problem constants
#define Bsz 2
#define Sq  2048
#define Dm  512
#define Vv  32000
#define Ll  3
#define ROWS (Bsz*Sq)      // 4096
#define BD   (ROWS*Dm)     // 2097152
#define SSZ  (Bsz*Sq*Sq)   // 8388608
#define INV_SCALE 0.125f
#define NATTN 9            // attention instances (3 enc self, 3 dec self, 3 dec cross)

// ---------------- fp32 scratch ----------------
__device__ float g_x[BD];
__device__ float g_out[BD];
__device__ float g_h[BD];
__device__ float g_h2[BD];
__device__ float g_t[BD];
__device__ float g_a[BD];
__device__ float g_rowsum[ROWS];          // vocab softmax sums
__device__ float g_rs2[(long)ROWS*NATTN]; // attention softmax sums (one slice per attn)

// ---------------- fp16 scratch ----------------
__device__ __half sx[BD];          // encoder state
__device__ __half so[BD];          // decoder state
__device__ __half sh[BD];          // attn-out
__device__ __half sh2[BD];         // attn2-out
__device__ __half sqkv[3*BD];      // Q | K | (V slot)
__device__ __half sp[SSZ];         // unnormalized exp-probs
__device__ __half svt[BD];         // V^T  [b][Dm][Sq]
__device__ __half sw[(long)Vv*Dm]; // packed weights^T

// ================= helpers =================
__device__ __forceinline__ uint32_t smem_u32(const void* p) {
    uint32_t a;
    asm("{ .reg .u64 t; cvta.to.shared.u64 t, %1; cvt.u32.u64 %0, t; }" : "=r"(a) : "l"(p));
    return a;
}
#define CP_ASYNC(dst, src) asm volatile("cp.async.cg.shared.global [%0], [%1], 16;" :: "r"(dst), "l"(src) : "memory")
#define CP_COMMIT()        asm volatile("cp.async.commit_group;" ::: "memory")
#define CP_WAIT(n)         asm volatile("cp.async.wait_group %0;" :: "n"(n) : "memory")

__device__ __forceinline__ void ldmx4(uint32_t& r0, uint32_t& r1, uint32_t& r2, uint32_t& r3, uint32_t a) {
    asm volatile("ldmatrix.sync.aligned.m8n8.x4.shared.b16 {%0,%1,%2,%3}, [%4];"
                 : "=r"(r0), "=r"(r1), "=r"(r2), "=r"(r3) : "r"(a));
}
__device__ __forceinline__ void mma_f16(float* d, const uint32_t* a, const uint32_t* b) {
    asm volatile(
        "mma.sync.aligned.m16n8k16.row.col.f32.f16.f16.f32 "
        "{%0,%1,%2,%3}, {%4,%5,%6,%7}, {%8,%9}, {%0,%1,%2,%3};"
        : "+f"(d[0]), "+f"(d[1]), "+f"(d[2]), "+f"(d[3])
        : "r"(a[0]), "r"(a[1]), "r"(a[2]), "r"(a[3]), "r"(b[0]), "r"(b[1]));
}
// SW128 swizzle for an R-row x 64-half (128B/row) tile. c = 16B chunk 0..7.
__device__ __forceinline__ uint32_t swz(int r, int c) {
    return (uint32_t)(r * 128 + ((c ^ (r & 7)) * 16));
}

// ================= GEMM: C = alpha * A @ B^T (+bias), fp16 x fp16 ===========
// A: [M,K] fp16; B: [N,K] fp16; fp32 accum.
// BM=BN=128, BK=64, 128 threads (4 warps: 2 M x 2 N, warp tile 64x64),
// 3-stage cp.async smem pipeline + double-buffered register fragments, 96KB smem.
// OUTM: 0 = fp32, 1 = fp16,
//       2 = exp() fp32 + atomic row sums (vocab softmax),
//       3 = exp() fp16 + atomic row sums (attention softmax; rowsum idx bz*M+row).
// Fused-output: global col cg -> out + (cg/outDiv)*bufStride + row*outDiv + cg%outDiv.
// TRANSV: column-buffer == vbuf written transposed into Cvt (V^T).
#define TILEA 16384
#define TILEBB 16384
#define STAGEB (TILEA + TILEBB)
#define GEMM_SMEM (3*STAGEB)

template<int OUTM, bool HAS_BIAS, bool TRANSV>
__global__ void __launch_bounds__(128) gemm1(
    const __half* __restrict__ A, const __half* __restrict__ B,
    const float* __restrict__ bias,
    float* __restrict__ C, __half* __restrict__ Ch, __half* __restrict__ Cvt,
    float* __restrict__ rowsum,
    int M, int N, int K, float alpha, long sA, long sB, long sC,
    int outDiv, long bufStride, int vbuf)
{
    extern __shared__ char smem[];
    const uint32_t sb = smem_u32(smem);
    const int tid = threadIdx.x, lane = tid & 31, wid = tid >> 5;
    const int wm = wid >> 1, wn = wid & 1;          // 2 M-warps x 2 N-warps
    const int bz = blockIdx.z;
    A += (long)bz * sA;
    B += (long)bz * sB;

    const long rA0 = (long)blockIdx.y * 128;
    const long rB0 = (long)blockIdx.x * 128;

    uint32_t soff[8];
    long goff[8];
    #pragma unroll
    for (int i = 0; i < 8; i++) {
        const int q = tid + i * 128;
        soff[i] = swz(q >> 3, q & 7);
        goff[i] = (long)(q >> 3) * K + (q & 7) * 8;
    }
    const __half* gA = A + rA0 * K;
    const __half* gB = B + rB0 * K;

    float acc[4][8][4];
    #pragma unroll
    for (int i = 0; i < 4; i++)
        #pragma unroll
        for (int j = 0; j < 8; j++)
            #pragma unroll
            for (int q = 0; q < 4; q++) acc[i][j][q] = 0.f;

    const int nk = K >> 6;

    auto load_tile = [&](int st, int k0) {
        const uint32_t s = sb + st * STAGEB;
        #pragma unroll
        for (int i = 0; i < 8; i++) {
            CP_ASYNC(s + soff[i],         gA + goff[i] + k0);
            CP_ASYNC(s + TILEA + soff[i], gB + goff[i] + k0);
        }
    };

    load_tile(0, 0);  CP_COMMIT();
    load_tile(1, 64); CP_COMMIT();

    const int arow = wm * 64 + (lane & 15);
    const int brow = wn * 64 + ((lane >> 4) << 3) + (lane & 7);
    const int asel = (lane >> 4);
    const int bsel = ((lane >> 3) & 1);

    int st = 0;
    for (int kt = 0; kt < nk; kt++) {
        if (kt + 1 < nk) { CP_WAIT(1); } else { CP_WAIT(0); }
        __syncthreads();
        if (kt + 2 < nk) {
            int st2 = st + 2; if (st2 >= 3) st2 -= 3;
            load_tile(st2, (kt + 2) << 6);
            CP_COMMIT();
        }

        const uint32_t s0  = sb + st * STAGEB;
        const uint32_t sA0 = s0, sB0 = s0 + TILEA;

        uint32_t ah[2][4][4];
        uint32_t bh[2][8][2];

        auto ldfr = [&](int ks, int pb) {
            const int achk = ks * 2 + asel;
            const int bchk = ks * 2 + bsel;
            #pragma unroll
            for (int mi = 0; mi < 4; mi++) {
                const uint32_t off = swz(arow + mi * 16, achk);
                ldmx4(ah[pb][mi][0], ah[pb][mi][1], ah[pb][mi][2], ah[pb][mi][3], sA0 + off);
            }
            #pragma unroll
            for (int nj = 0; nj < 4; nj++) {
                const uint32_t off = swz(brow + nj * 16, bchk);
                uint32_t t0, t1, t2, t3;
                ldmx4(t0, t1, t2, t3, sB0 + off);
                bh[pb][2*nj][0] = t0; bh[pb][2*nj][1] = t1;
                bh[pb][2*nj+1][0] = t2; bh[pb][2*nj+1][1] = t3;
            }
        };

        ldfr(0, 0);
        #pragma unroll
        for (int ks = 0; ks < 4; ks++) {
            const int cur = ks & 1;
            if (ks < 3) ldfr(ks + 1, cur ^ 1);
            #pragma unroll
            for (int mi = 0; mi < 4; mi++)
                #pragma unroll
                for (int ni = 0; ni < 8; ni++)
                    mma_f16(acc[mi][ni], ah[cur][mi], bh[cur][ni]);
        }
        st++; if (st >= 3) st = 0;
    }

    // epilogue
    const int ctile = blockIdx.x * 128;
    const int buf   = ctile / outDiv;
    const int cb    = (ctile % outDiv) + wn * 64 + (lane & 3) * 2;
    const long rbase = rA0 + wm * 64 + (lane >> 2);
    const long base  = (long)bz * sC + (long)buf * bufStride;

    if (TRANSV && buf == vbuf) {
        #pragma unroll
        for (int mi = 0; mi < 4; mi++) {
            const long rt0 = rbase + mi * 16;
            const long rt1 = rt0 + 8;
            const long b0 = (rt0 >> 11) * ((long)Dm * Sq), p0 = rt0 & 2047;
            const long b1 = (rt1 >> 11) * ((long)Dm * Sq), p1 = rt1 & 2047;
            #pragma unroll
            for (int ni = 0; ni < 8; ni++) {
                const int cc = cb + ni * 8;
                Cvt[b0 + (long)cc * Sq + p0]       = __float2half(acc[mi][ni][0]);
                Cvt[b0 + (long)(cc + 1) * Sq + p0] = __float2half(acc[mi][ni][1]);
                Cvt[b1 + (long)cc * Sq + p1]       = __float2half(acc[mi][ni][2]);
                Cvt[b1 + (long)(cc + 1) * Sq + p1] = __float2half(acc[mi][ni][3]);
            }
        }
        return;
    }

    #pragma unroll
    for (int mi = 0; mi < 4; mi++) {
        float rs0 = 0.f, rs1 = 0.f;
        #pragma unroll
        for (int ni = 0; ni < 8; ni++) {
            const int cc = cb + ni * 8;
            float v00 = alpha * acc[mi][ni][0], v01 = alpha * acc[mi][ni][1];
            float v10 = alpha * acc[mi][ni][2], v11 = alpha * acc[mi][ni][3];
            if (HAS_BIAS) {
                v00 += bias[cc]; v01 += bias[cc + 1];
                v10 += bias[cc]; v11 += bias[cc + 1];
            }
            const long r0 = base + (rbase + mi * 16) * outDiv + cc;
            const long r1 = r0 + 8 * outDiv;
            if (OUTM == 0) {
                *(float2*)(C + r0) = {v00, v01};
                *(float2*)(C + r1) = {v10, v11};
            } else if (OUTM == 1) {
                *(__half2*)(Ch + r0) = __halves2half2(__float2half(v00), __float2half(v01));
                *(__half2*)(Ch + r1) = __halves2half2(__float2half(v10), __float2half(v11));
            } else {
                float e00 = __expf(v00), e01 = __expf(v01);
                float e10 = __expf(v10), e11 = __expf(v11);
                if (OUTM == 2) {
                    *(float2*)(C + r0) = {e00, e01};
                    *(float2*)(C + r1) = {e10, e11};
                } else {
                    *(__half2*)(Ch + r0) = __halves2half2(__float2half(e00), __float2half(e01));
                    *(__half2*)(Ch + r1) = __halves2half2(__float2half(e10), __float2half(e11));
                }
                rs0 += e00 + e01;
                rs1 += e10 + e11;
            }
        }
        if (OUTM == 2 || OUTM == 3) {
            #pragma unroll
            for (int o = 1; o < 4; o <<= 1) {
                rs0 += __shfl_xor_sync(0xffffffffu, rs0, o);
                rs1 += __shfl_xor_sync(0xffffffffu, rs1, o);
            }
            if ((lane & 3) == 0) {
                const long rr = (long)bz * M + rbase + mi * 16;
                atomicAdd(&rowsum[rr], rs0);
                atomicAdd(&rowsum[rr + 8], rs1);
            }
        }
    }
}

// normalize: probs = exp_vals * (1/rowsum[row])
__global__ void norml_kernel(float* __restrict__ data, const float* __restrict__ rowsum)
{
    long i = ((long)blockIdx.x * blockDim.x + threadIdx.x) * 4;
    const float inv = 1.f / rowsum[i / Vv];
    float4 v = *(float4*)(data + i);
    v.x *= inv; v.y *= inv; v.z *= inv; v.w *= inv;
    *(float4*)(data + i) = v;
}

// ================= conversion kernels =================
__global__ void convh(const float* __restrict__ in, __half* __restrict__ o, long n)
{
    long i = ((long)blockIdx.x * blockDim.x + threadIdx.x) * 4;
    if (i >= n) return;
    float4 v = *(const float4*)(in + i);
    __half2 a = __halves2half2(__float2half(v.x), __float2half(v.y));
    __half2 b = __halves2half2(__float2half(v.z), __float2half(v.w));
    *(uint2*)(o + i) = make_uint2(*(uint32_t*)&a, *(uint32_t*)&b);
}

// transpose + convert: fp32 [R,C] -> fp16 [C,R]
__global__ void __launch_bounds__(256) tconvh(
    const float* __restrict__ in, __half* __restrict__ o, int R, int C)
{
    __shared__ float t[32][33];
    const int c0 = blockIdx.x * 32, r0 = blockIdx.y * 32;
    const int tx = threadIdx.x, ty = threadIdx.y;
    #pragma unroll
    for (int j = 0; j < 32; j += 8)
        t[ty + j][tx] = in[(long)(r0 + ty + j) * C + c0 + tx];
    __syncthreads();
    #pragma unroll
    for (int j = 0; j < 32; j += 8) {
        long ofs = (long)(c0 + ty + j) * R + r0 + tx;
        o[ofs] = __float2half(t[tx][ty + j]);
    }
}

// batched transpose+convert of up to 3 square DxD weights
__global__ void __launch_bounds__(256) tconvh3(
    const float* __restrict__ w0, const float* __restrict__ w1, const float* __restrict__ w2,
    __half* __restrict__ o)
{
    __shared__ float t[32][33];
    const int z = blockIdx.z;
    const float* in = (z == 0) ? w0 : (z == 1) ? w1 : w2;
    __half* dst = o + (long)z * Dm * Dm;
    const int c0 = blockIdx.x * 32, r0 = blockIdx.y * 32;
    const int tx = threadIdx.x, ty = threadIdx.y;
    #pragma unroll
    for (int j = 0; j < 32; j += 8)
        t[ty + j][tx] = in[(long)(r0 + ty + j) * Dm + c0 + tx];
    __syncthreads();
    #pragma unroll
    for (int j = 0; j < 32; j += 8) {
        long ofs = (long)(c0 + ty + j) * Dm + r0 + tx;
        dst[ofs] = __float2half(t[tx][ty + j]);
    }
}

// ====== fused (rowscale?)+(silu?)+residual+LayerNorm, fp32 out + fp16 out ======
template<bool SILU, bool AFFINE, bool RS>
__global__ void __launch_bounds__(128) addln_kernel(
    const float* __restrict__ a, const float* __restrict__ res,
    const float* __restrict__ g, const float* __restrict__ bta,
    const float* __restrict__ rowsum,
    float* __restrict__ out, __half* __restrict__ oh)
{
    const int row = blockIdx.x;
    const int tid = threadIdx.x;
    float4 av = ((const float4*)(a   + (size_t)row * Dm))[tid];
    float4 rv = ((const float4*)(res + (size_t)row * Dm))[tid];
    float v[4] = {av.x, av.y, av.z, av.w};
    float r[4] = {rv.x, rv.y, rv.z, rv.w};
    const float rsc = RS ? (1.f / rowsum[row]) : 1.f;

    float s = 0.f, s2 = 0.f;
    #pragma unroll
    for (int i = 0; i < 4; i++) {
        float t = RS ? (v[i] * rsc) : v[i];
        t = SILU ? (t / (1.f + __expf(-t))) : t;
        t += r[i];
        v[i] = t;
        s += t; s2 += t * t;
    }
    __shared__ float ss[4], ss2[4];
    #pragma unroll
    for (int o = 16; o; o >>= 1) {
        s  += __shfl_xor_sync(0xffffffffu, s,  o);
        s2 += __shfl_xor_sync(0xffffffffu, s2, o);
    }
    const int w = tid >> 5, lane = tid & 31;
    if (lane == 0) { ss[w] = s; ss2[w] = s2; }
    __syncthreads();
    s  = ss[0]  + ss[1]  + ss[2]  + ss[3];
    s2 = ss2[0] + ss2[1] + ss2[2] + ss2[3];

    const float mean = s * (1.f / Dm);
    const float var  = s2 * (1.f / Dm) - mean * mean;
    const float inv  = rsqrtf(var + 1e-5f);

    float ov[4];
    #pragma unroll
    for (int i = 0; i < 4; i++) {
        float yv = (v[i] - mean) * inv;
        if (AFFINE) {
            const int c = tid * 4 + i;
            yv = yv * g[c] + bta[c];
        }
        ov[i] = yv;
    }
    float4 o4 = {ov[0], ov[1], ov[2], ov[3]};
    ((float4*)(out + (size_t)row * Dm))[tid] = o4;
    __half2 h0 = __halves2half2(__float2half(ov[0]), __float2half(ov[1]));
    __half2 h1 = __halves2half2(__float2half(ov[2]), __float2half(ov[3]));
    ((uint2*)(oh + (size_t)row * Dm))[tid] = make_uint2(*(uint32_t*)&h0, *(uint32_t*)&h1);
}

// ================= host-side orchestration =================
struct Ptrs {
    float *gx, *gout, *gh, *gh2, *gt, *ga, *grs, *grs2;
    __half *x1, *o1, *h1, *h21, *q1, *k1, *p1, *vt1, *w1;
};

static void G(const __half* A, const __half* B,
              const float* bias, float* C, __half* Ch, int outm,
              int M, int N, int K, float alpha, int batch,
              long sA, long sB, long sC,
              int outDiv = 0, long bufStride = 0, float* rowsum = nullptr)
{
    if (outDiv == 0) outDiv = N;
    dim3 grid(N / 128, M / 128, batch), block(128);
    if (outm == 3)      gemm1<3, false, false><<<grid, block, GEMM_SMEM>>>(A, B, bias, C, Ch, nullptr, rowsum, M, N, K, alpha, sA, sB, sC, outDiv, bufStride, -1);
    else if (outm == 2) gemm1<2, false, false><<<grid, block, GEMM_SMEM>>>(A, B, bias, C, Ch, nullptr, rowsum, M, N, K, alpha, sA, sB, sC, outDiv, bufStride, -1);
    else if (outm == 1) gemm1<1, false, false><<<grid, block, GEMM_SMEM>>>(A, B, bias, C, Ch, nullptr, nullptr, M, N, K, alpha, sA, sB, sC, outDiv, bufStride, -1);
    else if (bias)      gemm1<0, true , false><<<grid, block, GEMM_SMEM>>>(A, B, bias, C, Ch, nullptr, nullptr, M, N, K, alpha, sA, sB, sC, outDiv, bufStride, -1);
    else                gemm1<0, false, false><<<grid, block, GEMM_SMEM>>>(A, B, bias, C, Ch, nullptr, nullptr, M, N, K, alpha, sA, sB, sC, outDiv, bufStride, -1);
}

static void Gp(const __half* A, const __half* B, __half* Ch, __half* Cvt, int vbuf,
               int M, int N, int K)
{
    dim3 grid(N / 128, M / 128, 1), block(128);
    gemm1<1, false, true><<<grid, block, GEMM_SMEM>>>(A, B, nullptr, nullptr, Ch, Cvt, nullptr,
                                                      M, N, K, 1.f, 0, 0, 0, Dm, (long)BD, vbuf);
}

static void tconv(const float* in, __half* o, int R, int C) {
    dim3 grid(C / 32, R / 32), block(32, 8);
    tconvh<<<grid, block>>>(in, o, R, C);
}
static void tconvN(const float* w0, const float* w1, const float* w2, __half* o, int nz) {
    dim3 grid(Dm / 32, Dm / 32, nz), block(32, 8);
    tconvh3<<<grid, block>>>(w0, w1, w2, o);
}

// attention; rs2 is this instance's pre-zeroed rowsum slice
static void run_attn(const Ptrs& P, float* rs2,
                     const __half* q_in, const __half* c_in,
                     const float* wq, const float* wk, const float* wv,
                     const float* resid, float* outp, __half* out_h)
{
    const long DD = (long)Dm * Dm;
    if (q_in == c_in) {
        tconvN(wq, wk, wv, P.w1, 3);
        Gp(q_in, P.w1, P.q1, P.vt1, 2, ROWS, 3 * Dm, Dm);
    } else {
        // batch all three weight transposes; Q GEMM reads slice 0, KV slices 1-2
        tconvN(wq, wk, wv, P.w1, 3);
        G(q_in, P.w1, nullptr, nullptr, P.q1, 1, ROWS, Dm, Dm, 1.f, 1, 0, 0, 0);
        Gp(c_in, P.w1 + DD, P.k1, P.vt1, 1, ROWS, 2 * Dm, Dm);
    }

    // scores GEMM writes exp(score) fp16 + row sums (no separate softmax)
    G(P.q1, P.k1, nullptr, nullptr, P.p1, 3, Sq, Sq, Dm, INV_SCALE, Bsz,
      (long)Sq * Dm, (long)Sq * Dm, (long)Sq * Sq, 0, 0, rs2);
    // attn[b] = Pexp[b] @ V[b]  (unnormalized)
    G(P.p1, P.vt1, nullptr, P.ga, nullptr, 0, Sq, Dm, Sq, 1.f, Bsz,
      (long)Sq * Sq, (long)Sq * Dm, (long)Sq * Dm);
    // normalize by rowsum inside addln
    addln_kernel<false, false, true><<<ROWS, 128>>>(P.ga, resid, nullptr, nullptr, rs2, outp, out_h);
}

extern "C" void kernel_launch(void* const* d_in, const int* in_sizes, int n_in,
                              void* d_out, int out_size)
{
    const float* x       = (const float*)d_in[0];
    const float* y       = (const float*)d_in[1];
    const float* enc_wq  = (const float*)d_in[2];
    const float* enc_wk  = (const float*)d_in[3];
    const float* enc_wv  = (const float*)d_in[4];
    const float* enc_fw  = (const float*)d_in[5];
    const float* enc_fb  = (const float*)d_in[6];
    const float* enc_g   = (const float*)d_in[7];
    const float* enc_b   = (const float*)d_in[8];
    const float* dec_swq = (const float*)d_in[9];
    const float* dec_swk = (const float*)d_in[10];
    const float* dec_swv = (const float*)d_in[11];
    const float* dec_cwq = (const float*)d_in[12];
    const float* dec_cwk = (const float*)d_in[13];
    const float* dec_cwv = (const float*)d_in[14];
    const float* dec_fw  = (const float*)d_in[15];
    const float* dec_fb  = (const float*)d_in[16];
    const float* dec_g   = (const float*)d_in[17];
    const float* dec_b   = (const float*)d_in[18];
    const float* fc_w    = (const float*)d_in[19];

    cudaFuncSetAttribute(gemm1<0, false, false>, cudaFuncAttributeMaxDynamicSharedMemorySize, GEMM_SMEM);
    cudaFuncSetAttribute(gemm1<0, true , false>, cudaFuncAttributeMaxDynamicSharedMemorySize, GEMM_SMEM);
    cudaFuncSetAttribute(gemm1<1, false, false>, cudaFuncAttributeMaxDynamicSharedMemorySize, GEMM_SMEM);
    cudaFuncSetAttribute(gemm1<2, false, false>, cudaFuncAttributeMaxDynamicSharedMemorySize, GEMM_SMEM);
    cudaFuncSetAttribute(gemm1<3, false, false>, cudaFuncAttributeMaxDynamicSharedMemorySize, GEMM_SMEM);
    cudaFuncSetAttribute(gemm1<1, false, true >, cudaFuncAttributeMaxDynamicSharedMemorySize, GEMM_SMEM);

    Ptrs P;
    cudaGetSymbolAddress((void**)&P.gx,   g_x);
    cudaGetSymbolAddress((void**)&P.gout, g_out);
    cudaGetSymbolAddress((void**)&P.gh,   g_h);
    cudaGetSymbolAddress((void**)&P.gh2,  g_h2);
    cudaGetSymbolAddress((void**)&P.gt,   g_t);
    cudaGetSymbolAddress((void**)&P.ga,   g_a);
    cudaGetSymbolAddress((void**)&P.grs,  g_rowsum);
    cudaGetSymbolAddress((void**)&P.grs2, g_rs2);
    cudaGetSymbolAddress((void**)&P.x1,  sx);
    cudaGetSymbolAddress((void**)&P.o1,  so);
    cudaGetSymbolAddress((void**)&P.h1,  sh);
    cudaGetSymbolAddress((void**)&P.h21, sh2);
    cudaGetSymbolAddress((void**)&P.q1,  sqkv);
    P.k1 = P.q1 + BD;
    cudaGetSymbolAddress((void**)&P.p1,  sp);
    cudaGetSymbolAddress((void**)&P.vt1, svt);
    cudaGetSymbolAddress((void**)&P.w1,  sw);

    cudaMemcpyAsync(P.gx,   x, (size_t)BD * sizeof(float), cudaMemcpyDeviceToDevice);
    cudaMemcpyAsync(P.gout, y, (size_t)BD * sizeof(float), cudaMemcpyDeviceToDevice);
    cudaMemsetAsync(P.grs, 0, ROWS * sizeof(float));
    cudaMemsetAsync(P.grs2, 0, (size_t)ROWS * NATTN * sizeof(float));
    convh<<<(BD / 4 + 255) / 256, 256>>>(x, P.x1, BD);
    convh<<<(BD / 4 + 255) / 256, 256>>>(y, P.o1, BD);

    const long DD = (long)Dm * Dm;
    int attn_idx = 0;

    // -------- encoder stacks --------
    for (int i = 0; i < Ll; i++) {
        run_attn(P, P.grs2 + (long)(attn_idx++) * ROWS, P.x1, P.x1,
                 enc_wq + i * DD, enc_wk + i * DD, enc_wv + i * DD,
                 P.gx, P.gh, P.h1);
        tconv(enc_fw + i * DD, P.w1, Dm, Dm);
        G(P.h1, P.w1, enc_fb + i * Dm, P.gt, nullptr, 0, ROWS, Dm, Dm, 1.f, 1, 0, 0, 0);
        addln_kernel<true, true, false><<<ROWS, 128>>>(P.gt, P.gh, enc_g + i * Dm, enc_b + i * Dm, nullptr, P.gx, P.x1);
    }

    // -------- decoder stacks --------
    for (int i = 0; i < Ll; i++) {
        run_attn(P, P.grs2 + (long)(attn_idx++) * ROWS, P.x1, P.x1,
                 dec_swq + i * DD, dec_swk + i * DD, dec_swv + i * DD,
                 P.gx, P.gh, P.h1);
        run_attn(P, P.grs2 + (long)(attn_idx++) * ROWS, P.h1, P.o1,
                 dec_cwq + i * DD, dec_cwk + i * DD, dec_cwv + i * DD,
                 P.gh, P.gh2, P.h21);
        tconv(dec_fw + i * DD, P.w1, Dm, Dm);
        G(P.h21, P.w1, dec_fb + i * Dm, P.gt, nullptr, 0, ROWS, Dm, Dm, 1.f, 1, 0, 0, 0);
        addln_kernel<true, true, false><<<ROWS, 128>>>(P.gt, P.gh2, dec_g + i * Dm, dec_b + i * Dm, nullptr, P.gout, P.o1);
    }

    // -------- vocab head: GEMM writes exp(logits) + row sums, then normalize --------
    tconv(fc_w, P.w1, Dm, Vv);
    float* probs = (float*)d_out;
    G(P.o1, P.w1, nullptr, probs, nullptr, 2, ROWS, Vv, Dm, 1.f, 1, 0, 0, 0, 0, 0, P.grs);
    norml_kernel<<<(int)(((long)ROWS * Vv / 4) / 256), 256>>>(probs, P.grs);
}